// round 12
// baseline (speedup 1.0000x reference)
#include <cuda_runtime.h>
#include <cstdint>

// ============================================================================
// FrequencyToSpatialCrossAttention — fused k3+k5 (one X_s DRAM pass + L2 reuse).
//  k1 : Qg = mean(X_f)                               read 402MB
//  k2a/k2b: projections; zero g_y                    tiny
//  k35: per 8x32 strip: scores (LDG-direct) -> softmax in smem ->
//       y accum (cp.async tiles, x re-read rides L2) read 402MB (+L2 pass)
//  k6a/k6b: output projections                       tiny
//  k7 : broadcast                                    write 402MB
// ============================================================================

#define BATCH 4
#define CDIM  384
#define NH    8
#define NPIX  65536

typedef unsigned long long ull;

__device__ __forceinline__ ull pk(float x, float y) {
    ull r; asm("mov.b64 %0, {%1,%2};" : "=l"(r) : "f"(x), "f"(y)); return r;
}
__device__ __forceinline__ void upk(ull v, float& x, float& y) {
    asm("mov.b64 {%0,%1}, %2;" : "=f"(x), "=f"(y) : "l"(v));
}
__device__ __forceinline__ ull ffma2(ull a, ull b, ull c) {
    ull d; asm("fma.rn.f32x2 %0, %1, %2, %3;" : "=l"(d) : "l"(a), "l"(b), "l"(c));
    return d;
}
__device__ __forceinline__ uint32_t s2u(const void* p) {
    uint32_t a;
    asm("{ .reg .u64 t; cvta.to.shared.u64 t, %1; cvt.u32.u64 %0, t; }"
        : "=r"(a) : "l"(p));
    return a;
}
__device__ __forceinline__ void cpa16(uint32_t dst, const void* src) {
    asm volatile("cp.async.cg.shared.global [%0], [%1], 16;" :: "r"(dst), "l"(src));
}

__device__ float g_Qg [BATCH*CDIM];
__device__ float g_qf [BATCH*CDIM];
__device__ float g_A  [BATCH*CDIM*NH];   // [b][c][h], scale folded
__device__ float g_y  [BATCH*NH*CDIM];
__device__ float g_pre[BATCH*CDIM];
__device__ float g_out[BATCH*CDIM];

// ---------------------------------------------------------------- k1: Qg mean
__global__ void k1_mean(const float* __restrict__ Xf) {
    int bc = blockIdx.x;
    const float4* src = (const float4*)Xf + (size_t)bc * 16384;
    float s0 = 0.f, s1 = 0.f;
    #pragma unroll 8
    for (int i = threadIdx.x; i < 16384; i += 1024) {
        float4 a = src[i], b = src[i + 512];
        s0 += (a.x + a.y) + (a.z + a.w);
        s1 += (b.x + b.y) + (b.z + b.w);
    }
    float s = s0 + s1;
    __shared__ float red[512];
    red[threadIdx.x] = s;
    __syncthreads();
    for (int o = 256; o > 0; o >>= 1) {
        if (threadIdx.x < o) red[threadIdx.x] += red[threadIdx.x + o];
        __syncthreads();
    }
    if (threadIdx.x == 0) g_Qg[bc] = red[0] * (1.f / 65536.f);
}

// -------------------------------------- k2a: qf = Qg@Wq^T + bq  (coalesced)
__global__ void k2a(const float* __restrict__ Wq, const float* __restrict__ bq) {
    int b = blockIdx.x, tid = threadIdx.x;
    __shared__ float sq[CDIM];
    for (int i = tid; i < CDIM; i += 256) sq[i] = g_Qg[b * CDIM + i];
    __syncthreads();
    int wid = tid >> 5, lane = tid & 31;
    #pragma unroll
    for (int cc = 0; cc < 4; cc++) {
        int c = blockIdx.y * 32 + wid * 4 + cc;
        const float* w = Wq + (size_t)c * CDIM;
        float s = 0.f;
        #pragma unroll
        for (int k = 0; k < 12; k++) s += w[lane + 32 * k] * sq[lane + 32 * k];
        #pragma unroll
        for (int o = 16; o > 0; o >>= 1) s += __shfl_xor_sync(0xffffffffu, s, o);
        if (lane == 0) g_qf[b * CDIM + c] = s + bq[c];
    }
}

// ----------------- k2b: A[b,c,h] = scale * qf_h . Wk_h[:,c]; zero g_y
__global__ void k2b(const float* __restrict__ Wk) {
    int b = blockIdx.x, tid = threadIdx.x;
    __shared__ float sq[CDIM];
    for (int i = tid; i < CDIM; i += 256) sq[i] = g_qf[b * CDIM + i];
    __syncthreads();
    int c = blockIdx.y * 32 + (tid & 31);
    int h = tid >> 5;
    float a = 0.f;
    #pragma unroll 8
    for (int d = 0; d < 48; d++)
        a += sq[h * 48 + d] * Wk[(size_t)(h * 48 + d) * CDIM + c];
    g_A[(size_t)(b * CDIM + c) * 8 + h] = a * 0.14433756729740643f;  // 48^-0.5
    if (blockIdx.y == 0)
        for (int i = tid; i < NH * CDIM; i += 256) g_y[b * NH * CDIM + i] = 0.f;
}

// ------------------- k35: fused scores + softmax + y;  strip = 8 rows x 32 cols
// grid 1024 = 4b * 32sr * 8st, 256 threads, 3 CTA/SM.
// Phase A: scores LDG-direct (1 px/thread), softmax in smem (weights in sS).
// Phase B: 6 c-chunks x 4 tiles (64ch x 64px), cp.async double-buffered;
//          x re-read is L2-hot; fold into smem then atomicAdd to g_y.
__global__ void __launch_bounds__(256, 3) k35_fused(const float* __restrict__ Xs) {
    __shared__ float sA[CDIM * 8];    // 12KB  [c][h]
    __shared__ float sS[8 * 264];     // 8.25KB scores->weights [h][256] pitch 264
    __shared__ float xb[2][64 * 68];  // 34KB  x tiles, pitch 68

    int bx = blockIdx.x;
    int b  = bx >> 8;
    int rem = bx & 255;
    int sr = rem >> 3;                // window row 0..31
    int st = rem & 7;                 // 32-col strip 0..7
    int t = threadIdx.x;

    for (int i = t; i < CDIM * 8; i += 256) sA[i] = g_A[b * CDIM * 8 + i];
    __syncthreads();

    // ---------------- phase A: scores, 1 px/thread ----------------
    {
        int r = t >> 5, col = t & 31;
        int si = (sr * 8 + r + 252) & 255;
        int sj = (st * 32 + col + 252) & 255;
        const float* xp = Xs + (size_t)b * CDIM * NPIX + si * 256 + sj;

        ull acc[4];
        #pragma unroll
        for (int q = 0; q < 4; q++) acc[q] = pk(0.f, 0.f);

        const ulonglong2* sA2 = (const ulonglong2*)sA;
        #pragma unroll 8
        for (int c = 0; c < CDIM; c++) {
            float x = xp[(size_t)c << 16];
            ull xx = pk(x, x);
            ulonglong2 a01 = sA2[c * 2];
            ulonglong2 a23 = sA2[c * 2 + 1];
            acc[0] = ffma2(xx, a01.x, acc[0]);
            acc[1] = ffma2(xx, a01.y, acc[1]);
            acc[2] = ffma2(xx, a23.x, acc[2]);
            acc[3] = ffma2(xx, a23.y, acc[3]);
        }
        int p = r * 32 + col;
        #pragma unroll
        for (int q = 0; q < 4; q++) {
            float lo, hi; upk(acc[q], lo, hi);
            sS[(2 * q) * 264 + p]     = lo;
            sS[(2 * q + 1) * 264 + p] = hi;
        }
    }
    __syncthreads();

    // ---------------- softmax per window (in smem) ----------------
    if (t < 64) {
        int pair = t >> 1, sub = t & 1;
        int h = pair >> 2, win = pair & 3;
        int base = h * 264 + win * 8;
        float4 v[8];
        #pragma unroll
        for (int rr = 0; rr < 4; rr++) {
            int off = base + (sub * 4 + rr) * 32;
            v[rr * 2]     = *(const float4*)&sS[off];
            v[rr * 2 + 1] = *(const float4*)&sS[off + 4];
        }
        float m = -1e30f;
        #pragma unroll
        for (int q = 0; q < 8; q++)
            m = fmaxf(m, fmaxf(fmaxf(v[q].x, v[q].y), fmaxf(v[q].z, v[q].w)));
        m = fmaxf(m, __shfl_xor_sync(0xffffffffu, m, 1));
        float Z = 0.f;
        #pragma unroll
        for (int q = 0; q < 8; q++) {
            v[q].x = __expf(v[q].x - m); v[q].y = __expf(v[q].y - m);
            v[q].z = __expf(v[q].z - m); v[q].w = __expf(v[q].w - m);
            Z += (v[q].x + v[q].y) + (v[q].z + v[q].w);
        }
        Z += __shfl_xor_sync(0xffffffffu, Z, 1);
        float inv = 1.f / (Z * 1024.f);             // fold 1/nW
        #pragma unroll
        for (int rr = 0; rr < 4; rr++) {
            int off = base + (sub * 4 + rr) * 32;
            float4 e0 = v[rr * 2], e1 = v[rr * 2 + 1];
            e0.x *= inv; e0.y *= inv; e0.z *= inv; e0.w *= inv;
            e1.x *= inv; e1.y *= inv; e1.z *= inv; e1.w *= inv;
            *(float4*)&sS[off]     = e0;
            *(float4*)&sS[off + 4] = e1;
        }
    }
    __syncthreads();

    // ---------------- phase B: y accumulation ----------------
    uint32_t xb_u[2] = { s2u(&xb[0][0]), s2u(&xb[1][0]) };
    int cg = t & 31, wid = t >> 5;    // wid doubles as px-group (tg)

    // stage tile (cchunk cc, row-tile rr2 covering strip rows 2rr2,2rr2+1)
    auto stage = [&](int cc, int rr2, int buf) {
        #pragma unroll
        for (int j = 0; j < 4; j++) {
            int i = t + j * 256;
            int c = i >> 4, f4 = i & 15;
            int rowL = rr2 * 2 + (f4 >> 3);
            int gi = (sr * 8 + rowL + 252) & 255;
            int gj = (st * 32 + (f4 & 7) * 4 + 252) & 255;
            cpa16(xb_u[buf] + (uint32_t)(c * 68 + f4 * 4) * 4,
                  Xs + ((size_t)(b * CDIM + cc * 64 + c) << 16) + gi * 256 + gj);
        }
    };

    for (int cc = 0; cc < 6; cc++) {
        ull yacc[2][8];
        #pragma unroll
        for (int i = 0; i < 2; i++)
            #pragma unroll
            for (int h = 0; h < 8; h++) yacc[i][h] = pk(0.f, 0.f);

        stage(cc, 0, 0);
        asm volatile("cp.async.commit_group;");

        for (int rr2 = 0; rr2 < 4; rr2++) {
            if (rr2 + 1 < 4) stage(cc, rr2 + 1, (rr2 + 1) & 1);
            asm volatile("cp.async.commit_group;");   // empty on last iter
            // groups retire in commit order: <=1 outstanding => tile rr2 done
            asm volatile("cp.async.wait_group 1;" ::: "memory");
            __syncthreads();

            const float* xbuf = xb[rr2 & 1];
            #pragma unroll
            for (int g = 0; g < 2; g++) {
                int t4 = wid * 8 + g * 4;
                float4 xv0 = *(const float4*)&xbuf[cg * 68 + t4];
                float4 xv1 = *(const float4*)&xbuf[(cg + 32) * 68 + t4];
                ull x0l = pk(xv0.x, xv0.y), x0h = pk(xv0.z, xv0.w);
                ull x1l = pk(xv1.x, xv1.y), x1h = pk(xv1.z, xv1.w);
                #pragma unroll
                for (int hh = 0; hh < 2; hh++) {
                    ull wl[4], wh[4];
                    #pragma unroll
                    for (int q = 0; q < 4; q++) {
                        float4 wv = *(const float4*)&sS[(hh * 4 + q) * 264
                                                        + rr2 * 64 + t4];
                        wl[q] = pk(wv.x, wv.y); wh[q] = pk(wv.z, wv.w);
                    }
                    #pragma unroll
                    for (int q = 0; q < 4; q++) {
                        int h = hh * 4 + q;
                        yacc[0][h] = ffma2(x0l, wl[q], yacc[0][h]);
                        yacc[0][h] = ffma2(x0h, wh[q], yacc[0][h]);
                        yacc[1][h] = ffma2(x1l, wl[q], yacc[1][h]);
                        yacc[1][h] = ffma2(x1h, wh[q], yacc[1][h]);
                    }
                }
            }
            __syncthreads();   // compute done before buffer re-stage next iter
        }

        // fold: per-warp partials into xb[0], then one RED per (h,c)
        float* sred = &xb[0][0];
        #pragma unroll
        for (int i = 0; i < 2; i++)
            #pragma unroll
            for (int h = 0; h < 8; h++) {
                float lo, hi; upk(yacc[i][h], lo, hi);
                sred[wid * 512 + i * 256 + h * 32 + cg] = lo + hi;
            }
        __syncthreads();
        #pragma unroll
        for (int o = t; o < 512; o += 256) {
            float s = 0.f;
            #pragma unroll
            for (int w = 0; w < 8; w++) s += sred[w * 512 + o];
            int i = o >> 8, h = (o >> 5) & 7, cgx = o & 31;
            int c = cc * 64 + cgx + 32 * i;
            atomicAdd(&g_y[b * NH * CDIM + h * CDIM + c], s);
        }
        __syncthreads();   // sred reads done before next cchunk stages xb[0]
    }
}

// ---------------------------- k6a: pre = Wv@y + bv   (warp-per-row, coalesced)
__global__ void k6a(const float* __restrict__ Wv, const float* __restrict__ bv) {
    int b = blockIdx.x, tid = threadIdx.x;
    __shared__ float sy[NH * CDIM];
    for (int i = tid; i < NH * CDIM; i += 256) sy[i] = g_y[b * NH * CDIM + i];
    __syncthreads();
    int wid = tid >> 5, lane = tid & 31;
    #pragma unroll
    for (int cc = 0; cc < 4; cc++) {
        int c = blockIdx.y * 32 + wid * 4 + cc;
        int h = c / 48;
        const float* w = Wv + (size_t)c * CDIM;
        const float* yy = &sy[h * CDIM];
        float s = 0.f;
        #pragma unroll
        for (int k = 0; k < 12; k++) s += w[lane + 32 * k] * yy[lane + 32 * k];
        #pragma unroll
        for (int o = 16; o > 0; o >>= 1) s += __shfl_xor_sync(0xffffffffu, s, o);
        if (lane == 0) g_pre[b * CDIM + c] = s + bv[c];
    }
}

// ---------------------------- k6b: out = Wo@pre + bo
__global__ void k6b(const float* __restrict__ Wo, const float* __restrict__ bo) {
    int b = blockIdx.x, tid = threadIdx.x;
    __shared__ float sp[CDIM];
    for (int i = tid; i < CDIM; i += 256) sp[i] = g_pre[b * CDIM + i];
    __syncthreads();
    int wid = tid >> 5, lane = tid & 31;
    #pragma unroll
    for (int cc = 0; cc < 4; cc++) {
        int c = blockIdx.y * 32 + wid * 4 + cc;
        const float* w = Wo + (size_t)c * CDIM;
        float s = 0.f;
        #pragma unroll
        for (int k = 0; k < 12; k++) s += w[lane + 32 * k] * sp[lane + 32 * k];
        #pragma unroll
        for (int o = 16; o > 0; o >>= 1) s += __shfl_xor_sync(0xffffffffu, s, o);
        if (lane == 0) g_out[b * CDIM + c] = s + bo[c];
    }
}

// ------------------------------------------------------------- k7: broadcast
__global__ void k7_bcast(float* __restrict__ out) {
    int plane = blockIdx.x;
    int q = blockIdx.y;
    float v = g_out[plane];
    float4 vv = make_float4(v, v, v, v);
    float4* dst = (float4*)out + (size_t)plane * 16384 + q * 4096;
    #pragma unroll 4
    for (int i = threadIdx.x; i < 4096; i += 256) dst[i] = vv;
}

// ============================================================================
extern "C" void kernel_launch(void* const* d_in, const int* in_sizes, int n_in,
                              void* d_out, int out_size) {
    const float* Xf = (const float*)d_in[0];
    const float* Xs = (const float*)d_in[1];
    const float* Wq = (const float*)d_in[2];
    const float* bq = (const float*)d_in[3];
    const float* Wk = (const float*)d_in[4];
    // d_in[5] = bk: constant per (b,h) in scores, cancels in softmax
    const float* Wv = (const float*)d_in[6];
    const float* bv = (const float*)d_in[7];
    const float* Wo = (const float*)d_in[8];
    const float* bo = (const float*)d_in[9];

    k1_mean  <<<BATCH * CDIM, 512>>>(Xf);
    k2a      <<<dim3(BATCH, 12), 256>>>(Wq, bq);
    k2b      <<<dim3(BATCH, 12), 256>>>(Wk);
    k35_fused<<<1024, 256>>>(Xs);
    k6a      <<<dim3(BATCH, 12), 256>>>(Wv, bv);
    k6b      <<<dim3(BATCH, 12), 256>>>(Wo, bo);
    k7_bcast <<<dim3(BATCH * CDIM, 4), 256>>>((float*)d_out);
}